// round 2
// baseline (speedup 1.0000x reference)
#include <cuda_runtime.h>
#include <math.h>

#define Bn 64
#define Tn 400
#define Hn 256
#define En 128
#define Vn 50000
#define Xn 500

// output layout (concatenated fp32, tuple order)
#define OFF_FINAL 0
#define OFF_HS   (Bn*(Vn+Xn))
#define OFF_CS   (OFF_HS + Bn*Hn)
#define OFF_CT   (OFF_CS + Bn*Hn)
#define OFF_ATTN (OFF_CT + Bn*2*Hn)
#define OFF_PGEN (OFF_ATTN + Bn*Tn)
#define OFF_COV  (OFF_PGEN + Bn)

// device scratch (no allocations allowed)
__device__ float g_x[Bn*En];
__device__ float g_gates[Bn*4*Hn];
__device__ float g_dec[Bn*2*Hn];
__device__ float g_outhid[Bn*Hn];
__device__ float g_elog[Bn*Vn];     // exp(logit + bias)
__device__ float g_rowsum[Bn];

__device__ __forceinline__ float warp_sum(float v){
    #pragma unroll
    for (int o = 16; o > 0; o >>= 1) v += __shfl_xor_sync(0xffffffffu, v, o);
    return v;
}
__device__ __forceinline__ float sigmoidf_(float x){ return 1.0f / (1.0f + expf(-x)); }

__device__ __forceinline__ unsigned long long pack2(float x, float y){
    unsigned long long r; asm("mov.b64 %0, {%1,%2};" : "=l"(r) : "f"(x), "f"(y)); return r;
}
__device__ __forceinline__ void unpack2(unsigned long long a, float &x, float &y){
    asm("mov.b64 {%0,%1}, %2;" : "=f"(x), "=f"(y) : "l"(a));
}
__device__ __forceinline__ unsigned long long fma2_(unsigned long long a, unsigned long long b, unsigned long long c){
    unsigned long long d; asm("fma.rn.f32x2 %0, %1, %2, %3;" : "=l"(d) : "l"(a), "l"(b), "l"(c)); return d;
}

// ---- x = cat([c_t_1, emb[y]]) @ Wxc^T + bxc : warp per (j, 8-batch group) ----
__global__ void k_gemv_x(const int* __restrict__ y_t_1, const float* __restrict__ c_t_1,
                         const float* __restrict__ embedding, const float* __restrict__ Wxc,
                         const float* __restrict__ bxc){
    int w = (blockIdx.x * blockDim.x + threadIdx.x) >> 5;
    int lane = threadIdx.x & 31;
    if (w >= En * 8) return;
    int j = w >> 3;
    int b0 = (w & 7) * 8;
    int yi[8];
    #pragma unroll
    for (int bb = 0; bb < 8; bb++) yi[bb] = y_t_1[b0 + bb];
    float acc[8] = {0,0,0,0,0,0,0,0};
    const float* wr = Wxc + j * 640;
    for (int k = lane; k < 512; k += 32){
        float wv = wr[k];
        #pragma unroll
        for (int bb = 0; bb < 8; bb++)
            acc[bb] += c_t_1[(b0+bb)*512 + k] * wv;
    }
    for (int k = 512 + lane; k < 640; k += 32){
        float wv = wr[k];
        #pragma unroll
        for (int bb = 0; bb < 8; bb++)
            acc[bb] += embedding[yi[bb]*En + (k - 512)] * wv;
    }
    #pragma unroll
    for (int bb = 0; bb < 8; bb++){
        float s = warp_sum(acc[bb]);
        if (lane == 0) g_x[(b0+bb)*En + j] = s + bxc[j];
    }
}

// ---- gates = x@W_ih^T + h0@W_hh^T + b : warp per (j, 8-batch group) ----
__global__ void k_gemv_gates(const float* __restrict__ h0, const float* __restrict__ W_ih,
                             const float* __restrict__ W_hh, const float* __restrict__ b_ih,
                             const float* __restrict__ b_hh){
    int w = (blockIdx.x * blockDim.x + threadIdx.x) >> 5;
    int lane = threadIdx.x & 31;
    if (w >= 1024 * 8) return;
    int j = w >> 3;
    int b0 = (w & 7) * 8;
    float acc[8] = {0,0,0,0,0,0,0,0};
    const float* wr1 = W_ih + j * En;
    for (int k = lane; k < En; k += 32){
        float wv = wr1[k];
        #pragma unroll
        for (int bb = 0; bb < 8; bb++)
            acc[bb] += g_x[(b0+bb)*En + k] * wv;
    }
    const float* wr2 = W_hh + j * Hn;
    for (int k = lane; k < Hn; k += 32){
        float wv = wr2[k];
        #pragma unroll
        for (int bb = 0; bb < 8; bb++)
            acc[bb] += h0[(b0+bb)*Hn + k] * wv;
    }
    float bias = b_ih[j] + b_hh[j];
    #pragma unroll
    for (int bb = 0; bb < 8; bb++){
        float s = warp_sum(acc[bb]);
        if (lane == 0) g_gates[(b0+bb)*4*Hn + j] = s + bias;
    }
}

// ---- LSTM elementwise (+ zero row sums) ----
__global__ void k_lstm(const float* __restrict__ c0, float* __restrict__ out){
    int i = blockIdx.x * blockDim.x + threadIdx.x;
    if (i < Bn) g_rowsum[i] = 0.0f;
    if (i >= Bn*Hn) return;
    int b = i >> 8, h = i & 255;
    const float* gr = g_gates + b*4*Hn;
    float ig = sigmoidf_(gr[h]);
    float fg = sigmoidf_(gr[Hn + h]);
    float gg = tanhf(gr[2*Hn + h]);
    float og = sigmoidf_(gr[3*Hn + h]);
    float cs = fg * c0[i] + ig * gg;
    float hs = og * tanhf(cs);
    out[OFF_HS + i] = hs;
    out[OFF_CS + i] = cs;
}

// ---- dec_fea = [hs|cs] @ Wdp^T + bdp : warp per (j, 8-batch group) ----
__global__ void k_gemv_dec(const float* __restrict__ out, const float* __restrict__ Wdp,
                           const float* __restrict__ bdp){
    int w = (blockIdx.x * blockDim.x + threadIdx.x) >> 5;
    int lane = threadIdx.x & 31;
    if (w >= 512 * 8) return;
    int j = w >> 3;
    int b0 = (w & 7) * 8;
    float acc[8] = {0,0,0,0,0,0,0,0};
    const float* wr = Wdp + j * 512;
    for (int k = lane; k < Hn; k += 32){
        float wv = wr[k];
        #pragma unroll
        for (int bb = 0; bb < 8; bb++)
            acc[bb] += out[OFF_HS + (b0+bb)*Hn + k] * wv;
    }
    for (int k = Hn + lane; k < 512; k += 32){
        float wv = wr[k];
        #pragma unroll
        for (int bb = 0; bb < 8; bb++)
            acc[bb] += out[OFF_CS + (b0+bb)*Hn + (k - Hn)] * wv;
    }
    #pragma unroll
    for (int bb = 0; bb < 8; bb++){
        float s = warp_sum(acc[bb]);
        if (lane == 0) g_dec[(b0+bb)*512 + j] = s + bdp[j];
    }
}

// ---- fused attention: scores + softmax + attn + c_t + p_gen (block per b) ----
__global__ void __launch_bounds__(1024) k_attn(const float* __restrict__ ef,
                                               const float* __restrict__ eo,
                                               const float* __restrict__ Wv,
                                               const float* __restrict__ mask,
                                               const float* __restrict__ stmt,
                                               const float* __restrict__ Wpg,
                                               const float* __restrict__ bpg,
                                               float* __restrict__ out){
    int b = blockIdx.x;
    int tid = threadIdx.x;
    int lane = tid & 31;
    int wid = tid >> 5;
    __shared__ float dec_s[512], wv_s[512];
    __shared__ float scores_s[Tn], attn_s[Tn], ct_s[512];
    __shared__ float red[1024];

    if (tid < 512){
        dec_s[tid] = g_dec[b*512 + tid];
        wv_s[tid]  = Wv[tid];
    }
    __syncthreads();

    // phase 1: scores[t] = Wv . tanh(ef[b,t,:] + dec)
    for (int t = wid; t < Tn; t += 32){
        const float* efr = ef + ((size_t)b * Tn + t) * 512;
        float acc = 0.0f;
        #pragma unroll 4
        for (int n = lane; n < 512; n += 32)
            acc += wv_s[n] * tanhf(efr[n] + dec_s[n]);
        acc = warp_sum(acc);
        if (lane == 0) scores_s[t] = acc;
    }
    __syncthreads();

    // phase 2: softmax + mask + renorm + stmt
    float s = (tid < Tn) ? scores_s[tid] : -1e30f;
    red[tid] = s; __syncthreads();
    for (int k = 512; k > 0; k >>= 1){ if (tid < k) red[tid] = fmaxf(red[tid], red[tid+k]); __syncthreads(); }
    float mx = red[0]; __syncthreads();
    float e = (tid < Tn) ? expf(s - mx) : 0.0f;
    red[tid] = e; __syncthreads();
    for (int k = 512; k > 0; k >>= 1){ if (tid < k) red[tid] += red[tid+k]; __syncthreads(); }
    float s1 = red[0]; __syncthreads();
    float mk = (tid < Tn) ? mask[b*Tn + tid] : 0.0f;
    float a = e / s1 * mk;
    red[tid] = a; __syncthreads();
    for (int k = 512; k > 0; k >>= 1){ if (tid < k) red[tid] += red[tid+k]; __syncthreads(); }
    float s2 = red[0]; __syncthreads();
    if (tid < Tn){
        float av = a / s2 + stmt[b*Tn + tid] * mk;
        attn_s[tid] = av;
        out[OFF_ATTN + b*Tn + tid] = av;
    }
    __syncthreads();

    // phase 3: c_t[n] = sum_t attn[t] * eo[b,t,n]  (two half-T partials)
    {
        int n = tid & 511;
        int half = tid >> 9;
        float acc = 0.0f;
        const float* eor = eo + ((size_t)b * Tn + half * 200) * 512 + n;
        #pragma unroll 4
        for (int tt = 0; tt < 200; tt++)
            acc += attn_s[half*200 + tt] * eor[(size_t)tt * 512];
        red[tid] = acc;
    }
    __syncthreads();
    if (tid < 512){
        float ct = red[tid] + red[tid + 512];
        ct_s[tid] = ct;
        out[OFF_CT + b*512 + tid] = ct;
    }
    __syncthreads();

    // phase 4: p_gen = sigmoid([c_t, hs, cs, x] . Wpg + bpg)  (warp 0)
    if (wid == 0){
        float acc = 0.0f;
        for (int k = lane; k < 1152; k += 32){
            float v;
            if (k < 512)        v = ct_s[k];
            else if (k < 768)   v = out[OFF_HS + b*Hn + (k - 512)];
            else if (k < 1024)  v = out[OFF_CS + b*Hn + (k - 768)];
            else                v = g_x[b*En + (k - 1024)];
            acc += v * Wpg[k];
        }
        acc = warp_sum(acc);
        if (lane == 0) out[OFF_PGEN + b] = sigmoidf_(acc + bpg[0]);
    }
}

// ---- outhid = [hs, c_t] @ Wo1^T + bo1 : warp per (j, 8-batch group) ----
__global__ void k_gemv_outhid(const float* __restrict__ out, const float* __restrict__ Wo1,
                              const float* __restrict__ bo1){
    int w = (blockIdx.x * blockDim.x + threadIdx.x) >> 5;
    int lane = threadIdx.x & 31;
    if (w >= Hn * 8) return;
    int j = w >> 3;
    int b0 = (w & 7) * 8;
    float acc[8] = {0,0,0,0,0,0,0,0};
    const float* wr = Wo1 + j * 768;
    for (int k = lane; k < Hn; k += 32){
        float wv = wr[k];
        #pragma unroll
        for (int bb = 0; bb < 8; bb++)
            acc[bb] += out[OFF_HS + (b0+bb)*Hn + k] * wv;
    }
    for (int k = Hn + lane; k < 768; k += 32){
        float wv = wr[k];
        #pragma unroll
        for (int bb = 0; bb < 8; bb++)
            acc[bb] += out[OFF_CT + (b0+bb)*512 + (k - Hn)] * wv;
    }
    #pragma unroll
    for (int bb = 0; bb < 8; bb++){
        float s = warp_sum(acc[bb]);
        if (lane == 0) g_outhid[(b0+bb)*Hn + j] = s + bo1[j];
    }
}

// ---- elog = exp(outhid @ Wo2^T + bo2), + atomic row sums ; f32x2 GEMM ----
__global__ void __launch_bounds__(256) k_logits(const float* __restrict__ W,
                                                const float* __restrict__ bias){
    __shared__ unsigned long long As2[32][65];  // [k][m], value duplicated in both halves
    __shared__ float Bs[32][264];               // [k][n]
    int tid = threadIdx.x;
    int vbase = blockIdx.x * 256;
    int tx = tid & 31, ty = tid >> 5;
    int m0 = ty * 8, n0 = tx * 8;
    unsigned long long acc[8][4];
    #pragma unroll
    for (int i = 0; i < 8; i++){
        #pragma unroll
        for (int q = 0; q < 4; q++) acc[i][q] = 0ull;
    }

    for (int kc = 0; kc < Hn; kc += 32){
        #pragma unroll
        for (int i = tid; i < 2048; i += 256){
            int m = i >> 5, kk = i & 31;
            float a = g_outhid[m*Hn + kc + kk];
            As2[kk][m] = pack2(a, a);
        }
        #pragma unroll
        for (int i4 = tid; i4 < 2048; i4 += 256){
            int row = i4 >> 3, k4 = i4 & 7;
            int v = vbase + row;
            float4 wv = (v < Vn) ? *(const float4*)&W[(size_t)v*Hn + kc + k4*4]
                                 : make_float4(0.f,0.f,0.f,0.f);
            Bs[k4*4+0][row] = wv.x; Bs[k4*4+1][row] = wv.y;
            Bs[k4*4+2][row] = wv.z; Bs[k4*4+3][row] = wv.w;
        }
        __syncthreads();
        #pragma unroll
        for (int kk = 0; kk < 32; kk++){
            ulonglong2 p0 = *(const ulonglong2*)&Bs[kk][n0];
            ulonglong2 p1 = *(const ulonglong2*)&Bs[kk][n0+4];
            #pragma unroll
            for (int i = 0; i < 8; i++){
                unsigned long long a2 = As2[kk][m0 + i];
                acc[i][0] = fma2_(a2, p0.x, acc[i][0]);
                acc[i][1] = fma2_(a2, p0.y, acc[i][1]);
                acc[i][2] = fma2_(a2, p1.x, acc[i][2]);
                acc[i][3] = fma2_(a2, p1.y, acc[i][3]);
            }
        }
        __syncthreads();
    }

    // epilogue: e = exp(acc + bias); store; warp-reduce per-row partial sums
    float bvals[8];
    #pragma unroll
    for (int j = 0; j < 8; j++){
        int v = vbase + n0 + j;
        bvals[j] = (v < Vn) ? bias[v] : 0.0f;
    }
    #pragma unroll
    for (int i = 0; i < 8; i++){
        int m = m0 + i;
        float vals[8];
        unpack2(acc[i][0], vals[0], vals[1]);
        unpack2(acc[i][1], vals[2], vals[3]);
        unpack2(acc[i][2], vals[4], vals[5]);
        unpack2(acc[i][3], vals[6], vals[7]);
        float psum = 0.0f;
        #pragma unroll
        for (int j = 0; j < 8; j++){
            int v = vbase + n0 + j;
            if (v < Vn){
                float ev = expf(vals[j] + bvals[j]);
                g_elog[(size_t)m*Vn + v] = ev;
                psum += ev;
            }
        }
        psum = warp_sum(psum);
        if (tx == 0) atomicAdd(&g_rowsum[m], psum);
    }
}

// ---- final_dist base: p_gen*softmax | extra_zeros ; plus coverage copy ----
__global__ void k_final(const float* __restrict__ extraz, const float* __restrict__ coverage,
                        float* __restrict__ out){
    int i = blockIdx.x * blockDim.x + threadIdx.x;
    if (i < Bn*Tn) out[OFF_COV + i] = coverage[i];
    if (i >= Bn*(Vn+Xn)) return;
    int b = i / (Vn+Xn);
    int v = i - b*(Vn+Xn);
    float r;
    if (v < Vn){
        float pg = out[OFF_PGEN + b];
        r = pg * g_elog[(size_t)b*Vn + v] / g_rowsum[b];
    } else {
        r = extraz[b*Xn + (v - Vn)];
    }
    out[OFF_FINAL + i] = r;
}

// ---- scatter: final[b, idx] += (1-p_gen)*attn ----
__global__ void k_scatter(const int* __restrict__ ebev, float* __restrict__ out){
    int i = blockIdx.x * blockDim.x + threadIdx.x;
    if (i >= Bn*Tn) return;
    int b = i / Tn;
    int ix = ebev[i];
    float pg = out[OFF_PGEN + b];
    float add = (1.0f - pg) * out[OFF_ATTN + i];
    atomicAdd(&out[OFF_FINAL + (size_t)b*(Vn+Xn) + ix], add);
}

extern "C" void kernel_launch(void* const* d_in, const int* in_sizes, int n_in,
                              void* d_out, int out_size){
    const int*   y_t_1    = (const int*)  d_in[0];
    const float* h0       = (const float*)d_in[1];
    const float* c0       = (const float*)d_in[2];
    const float* eo       = (const float*)d_in[3];
    const float* ef       = (const float*)d_in[4];
    const float* stmt     = (const float*)d_in[5];
    const float* mask     = (const float*)d_in[6];
    const float* c_t_1    = (const float*)d_in[7];
    const float* extraz   = (const float*)d_in[8];
    const int*   ebev     = (const int*)  d_in[9];
    const float* coverage = (const float*)d_in[10];
    const float* embedding = (const float*)d_in[n_in-16];
    const float* Wxc  = (const float*)d_in[n_in-15];
    const float* bxc  = (const float*)d_in[n_in-14];
    const float* W_ih = (const float*)d_in[n_in-13];
    const float* W_hh = (const float*)d_in[n_in-12];
    const float* b_ih = (const float*)d_in[n_in-11];
    const float* b_hh = (const float*)d_in[n_in-10];
    const float* Wdp  = (const float*)d_in[n_in-9];
    const float* bdp  = (const float*)d_in[n_in-8];
    const float* Wv   = (const float*)d_in[n_in-7];
    const float* Wpg  = (const float*)d_in[n_in-6];
    const float* bpg  = (const float*)d_in[n_in-5];
    const float* Wo1  = (const float*)d_in[n_in-4];
    const float* bo1  = (const float*)d_in[n_in-3];
    const float* Wo2  = (const float*)d_in[n_in-2];
    const float* bo2  = (const float*)d_in[n_in-1];
    float* out = (float*)d_out;

    k_gemv_x<<<(En*8*32 + 255)/256, 256>>>(y_t_1, c_t_1, embedding, Wxc, bxc);
    k_gemv_gates<<<(1024*8*32 + 255)/256, 256>>>(h0, W_ih, W_hh, b_ih, b_hh);
    k_lstm<<<(Bn*Hn + 255)/256, 256>>>(c0, out);
    k_gemv_dec<<<(512*8*32 + 255)/256, 256>>>(out, Wdp, bdp);
    k_attn<<<Bn, 1024>>>(ef, eo, Wv, mask, stmt, Wpg, bpg, out);
    k_gemv_outhid<<<(Hn*8*32 + 255)/256, 256>>>(out, Wo1, bo1);
    k_logits<<<(Vn + 255)/256, 256>>>(Wo2, bo2);
    k_final<<<(Bn*(Vn+Xn) + 255)/256, 256>>>(extraz, coverage, out);
    k_scatter<<<(Bn*Tn + 255)/256, 256>>>(ebev, out);
}